// round 1
// baseline (speedup 1.0000x reference)
#include <cuda_runtime.h>
#include <math.h>

// ---------------- problem constants ----------------
#define B_   8
#define S_   1024
#define E_   512
#define H_   8
#define D_   64
#define L_   4
#define KTOP 256
#define FIN  128
#define NCLS 10
#define QT   32          // queries per attention CTA

// ---------------- device scratch (no allocations allowed) ----------------
__device__ float g_h[(size_t)B_ * S_ * E_];
__device__ float g_q[(size_t)B_ * S_ * E_];
__device__ float g_k[(size_t)B_ * S_ * E_];
__device__ float g_v[(size_t)B_ * S_ * E_];
__device__ float g_o[(size_t)B_ * S_ * E_];
__device__ float g_pool[B_ * E_];

// ======================================================================
// SGEMM: C[M,N] = A[M,K] @ W[K,N] + bias[N]   (row-major, fp32)
// 128x128 tile, BK=32, 256 threads, 8x8 per thread.
// ======================================================================
#define BM 128
#define BN 128
#define BK 32

__global__ __launch_bounds__(256, 2)
void sgemm_bias(const float* __restrict__ A, const float* __restrict__ W,
                const float* __restrict__ bias, float* __restrict__ C,
                int M, int K, int N)
{
    __shared__ float As[BK][BM];   // transposed A tile
    __shared__ float Bs[BK][BN];

    const int t  = threadIdx.x;
    const int m0 = blockIdx.y * BM;
    const int n0 = blockIdx.x * BN;
    const int tx = t & 15;         // n-direction
    const int ty = t >> 4;         // m-direction

    float acc[8][8];
#pragma unroll
    for (int i = 0; i < 8; ++i)
#pragma unroll
        for (int j = 0; j < 8; ++j) acc[i][j] = 0.f;

    const float* Aptr = A + (size_t)m0 * K;
    const float* Wptr = W + n0;

    for (int k0 = 0; k0 < K; k0 += BK) {
        // load A tile (128 x 32) transposed into As
#pragma unroll
        for (int i = 0; i < 4; ++i) {
            int idx = t + i * 256;              // 0..1023
            int row = idx >> 3;                 // 0..127
            int c4  = (idx & 7) * 4;            // 0..28
            float4 v = *(const float4*)(Aptr + (size_t)row * K + k0 + c4);
            As[c4 + 0][row] = v.x;
            As[c4 + 1][row] = v.y;
            As[c4 + 2][row] = v.z;
            As[c4 + 3][row] = v.w;
        }
        // load W tile (32 x 128)
#pragma unroll
        for (int i = 0; i < 4; ++i) {
            int idx = t + i * 256;
            int row = idx >> 5;                 // 0..31
            int c4  = (idx & 31) * 4;           // 0..124
            *(float4*)&Bs[row][c4] = *(const float4*)(Wptr + (size_t)(k0 + row) * N + c4);
        }
        __syncthreads();

#pragma unroll
        for (int kk = 0; kk < BK; ++kk) {
            float a[8], b[8];
            *(float4*)&a[0] = *(float4*)&As[kk][ty * 8];
            *(float4*)&a[4] = *(float4*)&As[kk][ty * 8 + 4];
            *(float4*)&b[0] = *(float4*)&Bs[kk][tx * 8];
            *(float4*)&b[4] = *(float4*)&Bs[kk][tx * 8 + 4];
#pragma unroll
            for (int i = 0; i < 8; ++i)
#pragma unroll
                for (int j = 0; j < 8; ++j)
                    acc[i][j] += a[i] * b[j];
        }
        __syncthreads();
    }

    // epilogue with bias
    float bv[8];
#pragma unroll
    for (int j = 0; j < 8; ++j) bv[j] = bias[n0 + tx * 8 + j];

#pragma unroll
    for (int i = 0; i < 8; ++i) {
        float* Crow = C + (size_t)(m0 + ty * 8 + i) * N + n0 + tx * 8;
        float4 r0 = make_float4(acc[i][0] + bv[0], acc[i][1] + bv[1],
                                acc[i][2] + bv[2], acc[i][3] + bv[3]);
        float4 r1 = make_float4(acc[i][4] + bv[4], acc[i][5] + bv[5],
                                acc[i][6] + bv[6], acc[i][7] + bv[7]);
        *(float4*)(Crow)     = r0;
        *(float4*)(Crow + 4) = r1;
    }
}

// ======================================================================
// Sparse attention: one CTA per (b, h, 32-query tile).
// Computes full score rows, exact top-k (k-th largest) via radix select,
// masked softmax (unnormalized; 1/sum folded into PV epilogue), PV.
// ======================================================================

// dynamic smem layout (bytes)
#define SM_SSC   0                                  // [32][1024] f32 = 131072
#define SM_QS    (32 * 1024 * 4)                    // Qs_t[64][32]   =   8192
#define SM_KBUF  (SM_QS + 64 * 32 * 4)              // [64][132] f32  =  33792 (reused as V [64][68])
#define SM_HIST  (SM_KBUF + 64 * 132 * 4)           // [8][256] u32   =   8192
#define SM_SSUM  (SM_HIST + 8 * 256 * 4)            // [32] f32       =    128
#define SMEM_BYTES (SM_SSUM + 32 * 4)               // 181376

__device__ __forceinline__ unsigned fmap(float x) {
    unsigned u = __float_as_uint(x);
    return (u & 0x80000000u) ? ~u : (u | 0x80000000u);   // monotonic float->uint
}

__global__ __launch_bounds__(256, 1)
void attn_kernel()
{
    extern __shared__ char smraw[];
    float*    Ssc  = (float*)(smraw + SM_SSC);      // [32][1024]
    float*    Qs   = (float*)(smraw + SM_QS);       // Qs_t[dd][qi]  stride 32
    float*    Kbuf = (float*)(smraw + SM_KBUF);     // Ks_t[dd][kj]  stride 132 ; V: [kj][dd] stride 68
    unsigned* hist = (unsigned*)(smraw + SM_HIST);  // [8][256]
    float*    ssum = (float*)(smraw + SM_SSUM);     // [32]

    const int t   = threadIdx.x;
    const int gid = blockIdx.x;
    const int qt  = gid & 31;
    const int hh  = (gid >> 5) & 7;
    const int b   = gid >> 8;

    const float* Qg = g_q + ((size_t)(b * S_ + qt * QT)) * E_ + hh * D_;
    const float* Kg = g_k + ((size_t)b * S_) * E_ + hh * D_;
    const float* Vg = g_v + ((size_t)b * S_) * E_ + hh * D_;
    float*       Og = g_o + ((size_t)(b * S_ + qt * QT)) * E_ + hh * D_;

    // ---- load Q tile transposed: Qs[dd][qi] ----
#pragma unroll
    for (int i = 0; i < 2; ++i) {
        int idx = t + i * 256;                  // 0..511
        int qi  = idx >> 4;                     // 0..31
        int dd0 = (idx & 15) * 4;               // 0..60
        float4 v = *(const float4*)(Qg + (size_t)qi * E_ + dd0);
        Qs[(dd0 + 0) * 32 + qi] = v.x;
        Qs[(dd0 + 1) * 32 + qi] = v.y;
        Qs[(dd0 + 2) * 32 + qi] = v.z;
        Qs[(dd0 + 3) * 32 + qi] = v.w;
    }

    // ---- scores: S[32][1024] = (Q K^T) * scale ----
    const float scale = 0.125f;                 // 1/sqrt(64)
    const int kg  = t & 31;
    const int qg  = t >> 5;
    const int qi0 = qg * 4;
    const int kj0 = kg * 4;

    for (int kc = 0; kc < S_; kc += 128) {
        // load K chunk [128][64] transposed -> Kbuf[dd][kj] stride 132
#pragma unroll
        for (int i = 0; i < 8; ++i) {
            int idx = t + i * 256;              // 0..2047
            int kj  = idx >> 4;                 // 0..127
            int dd0 = (idx & 15) * 4;
            float4 v = *(const float4*)(Kg + (size_t)(kc + kj) * E_ + dd0);
            Kbuf[(dd0 + 0) * 132 + kj] = v.x;
            Kbuf[(dd0 + 1) * 132 + kj] = v.y;
            Kbuf[(dd0 + 2) * 132 + kj] = v.z;
            Kbuf[(dd0 + 3) * 132 + kj] = v.w;
        }
        __syncthreads();

        float acc[4][4];
#pragma unroll
        for (int i = 0; i < 4; ++i)
#pragma unroll
            for (int j = 0; j < 4; ++j) acc[i][j] = 0.f;

#pragma unroll 16
        for (int dd = 0; dd < 64; ++dd) {
            float4 qv = *(const float4*)&Qs[dd * 32 + qi0];
            float4 kv = *(const float4*)&Kbuf[dd * 132 + kj0];
            float qa[4] = {qv.x, qv.y, qv.z, qv.w};
            float kb[4] = {kv.x, kv.y, kv.z, kv.w};
#pragma unroll
            for (int i = 0; i < 4; ++i)
#pragma unroll
                for (int j = 0; j < 4; ++j)
                    acc[i][j] += qa[i] * kb[j];
        }
#pragma unroll
        for (int i = 0; i < 4; ++i) {
            float4 o = make_float4(acc[i][0] * scale, acc[i][1] * scale,
                                   acc[i][2] * scale, acc[i][3] * scale);
            *(float4*)&Ssc[(size_t)(qi0 + i) * 1024 + kc + kj0] = o;
        }
        __syncthreads();
    }

    // ---- per-query exact top-k threshold + softmax (warp w -> queries w*4..w*4+3) ----
    const int w    = t >> 5;
    const int lane = t & 31;
    unsigned* h8   = hist + w * 256;

    for (int qq = 0; qq < 4; ++qq) {
        const int qi = w * 4 + qq;
        float* row = Ssc + (size_t)qi * 1024;

        // row max
        float m = -1e30f;
#pragma unroll
        for (int i = 0; i < 32; ++i) m = fmaxf(m, row[lane + 32 * i]);
#pragma unroll
        for (int off = 16; off > 0; off >>= 1)
            m = fmaxf(m, __shfl_xor_sync(0xFFFFFFFFu, m, off));

        // radix select: value of the KTOP-th largest
        unsigned want = KTOP, prefix = 0;
#pragma unroll
        for (int byte = 3; byte >= 0; --byte) {
#pragma unroll
            for (int j = 0; j < 8; ++j) h8[lane * 8 + j] = 0;
            __syncwarp();
            const int shift = byte * 8;
            const unsigned hmask = (byte == 3) ? 0u : (0xFFFFFFFFu << (shift + 8));
#pragma unroll
            for (int i = 0; i < 32; ++i) {
                unsigned u = fmap(row[lane + 32 * i]);
                if ((u & hmask) == prefix)
                    atomicAdd(&h8[(u >> shift) & 255], 1u);
            }
            __syncwarp();
            unsigned c = 0;
#pragma unroll
            for (int j = 0; j < 8; ++j) c += h8[lane * 8 + j];
            unsigned sfx = c;                       // inclusive suffix sum over lanes
#pragma unroll
            for (int off = 1; off < 32; off <<= 1) {
                unsigned o = __shfl_down_sync(0xFFFFFFFFu, sfx, off);
                if (lane + off < 32) sfx += o;
            }
            const bool pred = (sfx >= want) && (sfx - c < want);
            const unsigned bal = __ballot_sync(0xFFFFFFFFu, pred);
            const int g = __ffs(bal) - 1;
            unsigned sfx_g = __shfl_sync(0xFFFFFFFFu, sfx, g);
            unsigned c_g   = __shfl_sync(0xFFFFFFFFu, c, g);
            unsigned selBin = 0, nwant = 0;
            if (lane == g) {
                unsigned rem = want - (sfx_g - c_g);
                unsigned cum = 0;
                for (int bin = 7; bin >= 0; --bin) {
                    unsigned hv = h8[g * 8 + bin];
                    cum += hv;
                    if (cum >= rem) { selBin = g * 8 + bin; nwant = rem - (cum - hv); break; }
                }
            }
            selBin = __shfl_sync(0xFFFFFFFFu, selBin, g);
            want   = __shfl_sync(0xFFFFFFFFu, nwant, g);
            prefix |= selBin << shift;
        }
        const unsigned uT = prefix;                 // exact k-th largest (mapped)

        // masked exp (unnormalized), accumulate sum
        float sum = 0.f;
#pragma unroll
        for (int i = 0; i < 32; ++i) {
            float x = row[lane + 32 * i];
            float p = (fmap(x) >= uT) ? expf(x - m) : 0.f;
            row[lane + 32 * i] = p;
            sum += p;
        }
#pragma unroll
        for (int off = 16; off > 0; off >>= 1)
            sum += __shfl_xor_sync(0xFFFFFFFFu, sum, off);
        if (lane == 0) ssum[qi] = sum;
    }
    __syncthreads();

    // ---- PV: O[32][64] = P @ V  (V chunks of 64 keys in smem, stride 68) ----
    const int dd4 = (t & 15) * 4;
    const int qp  = t >> 4;                         // 0..15
    const int qa0 = qp * 2;
    float oacc[2][4];
#pragma unroll
    for (int i = 0; i < 2; ++i)
#pragma unroll
        for (int j = 0; j < 4; ++j) oacc[i][j] = 0.f;

    for (int vc = 0; vc < S_; vc += 64) {
#pragma unroll
        for (int i = 0; i < 4; ++i) {
            int idx = t + i * 256;                  // 0..1023
            int kj  = idx >> 4;                     // 0..63
            int dd0 = (idx & 15) * 4;
            float4 v = *(const float4*)(Vg + (size_t)(vc + kj) * E_ + dd0);
            *(float4*)&Kbuf[kj * 68 + dd0] = v;
        }
        __syncthreads();
#pragma unroll 8
        for (int j = 0; j < 64; ++j) {
            float4 v = *(const float4*)&Kbuf[j * 68 + dd4];
            float p0 = Ssc[(size_t)qa0 * 1024 + vc + j];
            float p1 = Ssc[(size_t)(qa0 + 1) * 1024 + vc + j];
            oacc[0][0] += p0 * v.x; oacc[0][1] += p0 * v.y;
            oacc[0][2] += p0 * v.z; oacc[0][3] += p0 * v.w;
            oacc[1][0] += p1 * v.x; oacc[1][1] += p1 * v.y;
            oacc[1][2] += p1 * v.z; oacc[1][3] += p1 * v.w;
        }
        __syncthreads();
    }

    const float inv0 = 1.f / ssum[qa0];
    const float inv1 = 1.f / ssum[qa0 + 1];
    float4 r0 = make_float4(oacc[0][0] * inv0, oacc[0][1] * inv0,
                            oacc[0][2] * inv0, oacc[0][3] * inv0);
    float4 r1 = make_float4(oacc[1][0] * inv1, oacc[1][1] * inv1,
                            oacc[1][2] * inv1, oacc[1][3] * inv1);
    *(float4*)(Og + (size_t)qa0 * E_ + dd4)       = r0;
    *(float4*)(Og + (size_t)(qa0 + 1) * E_ + dd4) = r1;
}

// ======================================================================
// mean pool over S, then final FC
// ======================================================================
__global__ void meanpool_k(const float* __restrict__ h, float* __restrict__ pool)
{
    __shared__ float red[512];
    const int b = blockIdx.y;
    const int e = blockIdx.x * 128 + (threadIdx.x & 127);
    const int slice = threadIdx.x >> 7;            // 0..3
    const float* base = h + (size_t)b * S_ * E_ + e;
    float s = 0.f;
#pragma unroll 8
    for (int i = 0; i < 256; ++i)
        s += base[(size_t)(slice * 256 + i) * E_];
    red[threadIdx.x] = s;
    __syncthreads();
    if (slice == 0) {
        float tot = red[threadIdx.x] + red[threadIdx.x + 128] +
                    red[threadIdx.x + 256] + red[threadIdx.x + 384];
        pool[b * E_ + e] = tot * (1.f / (float)S_);
    }
}

__global__ void fc_k(const float* __restrict__ pool, const float* __restrict__ w,
                     const float* __restrict__ bias, float* __restrict__ out)
{
    int t = threadIdx.x;
    if (t >= B_ * NCLS) return;
    int b = t / NCLS, c = t % NCLS;
    float s = bias[c];
    const float* p = pool + b * E_;
#pragma unroll 8
    for (int k = 0; k < E_; ++k)
        s += p[k] * w[k * NCLS + c];
    out[t] = s;
}

// ======================================================================
// launch
// ======================================================================
extern "C" void kernel_launch(void* const* d_in, const int* in_sizes, int n_in,
                              void* d_out, int out_size)
{
    (void)in_sizes; (void)n_in; (void)out_size;

    const float* x     = (const float*)d_in[0];
    const float* emb_w = (const float*)d_in[1];
    const float* emb_b = (const float*)d_in[2];
    const float* Wq    = (const float*)d_in[3];
    const float* Wk    = (const float*)d_in[4];
    const float* Wv    = (const float*)d_in[5];
    const float* Wo    = (const float*)d_in[6];
    const float* bq    = (const float*)d_in[7];
    const float* bk    = (const float*)d_in[8];
    const float* bv    = (const float*)d_in[9];
    const float* bo    = (const float*)d_in[10];
    const float* fc_w  = (const float*)d_in[11];
    const float* fc_b  = (const float*)d_in[12];
    float* out = (float*)d_out;

    float *h, *q, *k, *v, *o, *pool;
    cudaGetSymbolAddress((void**)&h,    g_h);
    cudaGetSymbolAddress((void**)&q,    g_q);
    cudaGetSymbolAddress((void**)&k,    g_k);
    cudaGetSymbolAddress((void**)&v,    g_v);
    cudaGetSymbolAddress((void**)&o,    g_o);
    cudaGetSymbolAddress((void**)&pool, g_pool);

    cudaFuncSetAttribute(attn_kernel, cudaFuncAttributeMaxDynamicSharedMemorySize, SMEM_BYTES);

    const int M = B_ * S_;                          // 8192
    dim3 ggrid(E_ / BN, M / BM);                    // (4, 64)

    // embed: h = x @ emb_w + emb_b
    sgemm_bias<<<ggrid, 256>>>(x, emb_w, emb_b, h, M, FIN, E_);

    for (int l = 0; l < L_; ++l) {
        const size_t wo = (size_t)l * E_ * E_;
        const size_t bo_ = (size_t)l * E_;
        sgemm_bias<<<ggrid, 256>>>(h, Wq + wo, bq + bo_, q, M, E_, E_);
        sgemm_bias<<<ggrid, 256>>>(h, Wk + wo, bk + bo_, k, M, E_, E_);
        sgemm_bias<<<ggrid, 256>>>(h, Wv + wo, bv + bo_, v, M, E_, E_);
        attn_kernel<<<B_ * H_ * (S_ / QT), 256, SMEM_BYTES>>>();
        sgemm_bias<<<ggrid, 256>>>(o, Wo + wo, bo + bo_, h, M, E_, E_);
    }

    meanpool_k<<<dim3(E_ / 128, B_), 512>>>(h, pool);
    fc_k<<<1, 128>>>(pool, fc_w, fc_b, out);
}

// round 2
// speedup vs baseline: 1.2852x; 1.2852x over previous
#include <cuda_runtime.h>
#include <math.h>

// ---------------- problem constants ----------------
#define B_   8
#define S_   1024
#define E_   512
#define H_   8
#define D_   64
#define L_   4
#define KTOP 256
#define FIN  128
#define NCLS 10
#define QT   32          // queries per attention CTA

// ---------------- device scratch (no allocations allowed) ----------------
__device__ float g_h[(size_t)B_ * S_ * E_];
__device__ float g_q[(size_t)B_ * S_ * E_];
__device__ float g_k[(size_t)B_ * S_ * E_];
__device__ float g_v[(size_t)B_ * S_ * E_];
__device__ float g_o[(size_t)B_ * S_ * E_];
__device__ float g_pool[B_ * E_];

// ======================================================================
// SGEMM core: C[M,N] = A[M,K] @ W[K,N] + bias[N]   (row-major, fp32)
// 128x128 tile, BK=32, 256 threads, 8x8 per thread.
// ======================================================================
#define BM 128
#define BN 128
#define BK 32

__device__ __forceinline__
void sgemm_body(const float* __restrict__ A, const float* __restrict__ W,
                const float* __restrict__ bias, float* __restrict__ C,
                int M, int K, int N)
{
    __shared__ float As[BK][BM];   // transposed A tile
    __shared__ float Bs[BK][BN];

    const int t  = threadIdx.x;
    const int m0 = blockIdx.y * BM;
    const int n0 = blockIdx.x * BN;
    const int tx = t & 15;         // n-direction
    const int ty = t >> 4;         // m-direction

    float acc[8][8];
#pragma unroll
    for (int i = 0; i < 8; ++i)
#pragma unroll
        for (int j = 0; j < 8; ++j) acc[i][j] = 0.f;

    const float* Aptr = A + (size_t)m0 * K;
    const float* Wptr = W + n0;

    for (int k0 = 0; k0 < K; k0 += BK) {
#pragma unroll
        for (int i = 0; i < 4; ++i) {
            int idx = t + i * 256;              // 0..1023
            int row = idx >> 3;                 // 0..127
            int c4  = (idx & 7) * 4;            // 0..28
            float4 v = *(const float4*)(Aptr + (size_t)row * K + k0 + c4);
            As[c4 + 0][row] = v.x;
            As[c4 + 1][row] = v.y;
            As[c4 + 2][row] = v.z;
            As[c4 + 3][row] = v.w;
        }
#pragma unroll
        for (int i = 0; i < 4; ++i) {
            int idx = t + i * 256;
            int row = idx >> 5;                 // 0..31
            int c4  = (idx & 31) * 4;           // 0..124
            *(float4*)&Bs[row][c4] = *(const float4*)(Wptr + (size_t)(k0 + row) * N + c4);
        }
        __syncthreads();

#pragma unroll
        for (int kk = 0; kk < BK; ++kk) {
            float a[8], b[8];
            *(float4*)&a[0] = *(float4*)&As[kk][ty * 8];
            *(float4*)&a[4] = *(float4*)&As[kk][ty * 8 + 4];
            *(float4*)&b[0] = *(float4*)&Bs[kk][tx * 8];
            *(float4*)&b[4] = *(float4*)&Bs[kk][tx * 8 + 4];
#pragma unroll
            for (int i = 0; i < 8; ++i)
#pragma unroll
                for (int j = 0; j < 8; ++j)
                    acc[i][j] += a[i] * b[j];
        }
        __syncthreads();
    }

    float bv[8];
#pragma unroll
    for (int j = 0; j < 8; ++j) bv[j] = bias[n0 + tx * 8 + j];

#pragma unroll
    for (int i = 0; i < 8; ++i) {
        float* Crow = C + (size_t)(m0 + ty * 8 + i) * N + n0 + tx * 8;
        float4 r0 = make_float4(acc[i][0] + bv[0], acc[i][1] + bv[1],
                                acc[i][2] + bv[2], acc[i][3] + bv[3]);
        float4 r1 = make_float4(acc[i][4] + bv[4], acc[i][5] + bv[5],
                                acc[i][6] + bv[6], acc[i][7] + bv[7]);
        *(float4*)(Crow)     = r0;
        *(float4*)(Crow + 4) = r1;
    }
}

__global__ __launch_bounds__(256, 2)
void sgemm_bias(const float* __restrict__ A, const float* __restrict__ W,
                const float* __restrict__ bias, float* __restrict__ C,
                int M, int K, int N)
{
    sgemm_body(A, W, bias, C, M, K, N);
}

// fused Q/K/V projection: blockIdx.z selects which of the three GEMMs
__global__ __launch_bounds__(256, 2)
void sgemm_qkv(const float* __restrict__ A,
               const float* __restrict__ Wq, const float* __restrict__ Wk,
               const float* __restrict__ Wv,
               const float* __restrict__ bq, const float* __restrict__ bk,
               const float* __restrict__ bv,
               float* __restrict__ q, float* __restrict__ k, float* __restrict__ v)
{
    const float* W; const float* bb; float* C;
    if (blockIdx.z == 0)      { W = Wq; bb = bq; C = q; }
    else if (blockIdx.z == 1) { W = Wk; bb = bk; C = k; }
    else                      { W = Wv; bb = bv; C = v; }
    sgemm_body(A, W, bb, C, B_ * S_, E_, E_);
}

// ======================================================================
// Sparse attention v2: one CTA per (b, h, 32-query tile), 512 threads.
//  - scores QK^T with XOR-swizzled K transpose in smem
//  - exact top-k via per-warp register binary search (no atomics)
//  - softmax fused in registers, 1/sum folded into stored probabilities
//  - PV as register-tiled GEMM with 4-way j-split + smem reduction
// ======================================================================

// smem (floats): Ssc[32*1024] | Qs[64*32] | Kb[64*256] (reused as V[256][64], then red[4*128*16])
#define SSC_F   (32 * 1024)
#define QS_F    (64 * 32)
#define KB_F    (64 * 256)
#define SMEM_BYTES ((SSC_F + QS_F + KB_F) * 4)   // 204800

__device__ __forceinline__ unsigned fmap(float x) {
    unsigned u = __float_as_uint(x);
    return (u & 0x80000000u) ? ~u : (u | 0x80000000u);   // order-preserving
}
__device__ __forceinline__ float unfmap(unsigned u) {
    return (u & 0x80000000u) ? __uint_as_float(u & 0x7FFFFFFFu)
                             : __uint_as_float(~u);
}

__global__ __launch_bounds__(512, 1)
void attn_kernel()
{
    extern __shared__ float sm[];
    float* Ssc = sm;                 // [32][1024]
    float* Qs  = sm + SSC_F;         // Qs_t[dd][qi], stride 32
    float* Kb  = Qs + QS_F;          // swizzled Ks_t[dd][256] ; later V[256][64] ; later red

    const int t   = threadIdx.x;
    const int gid = blockIdx.x;
    const int qt  = gid & 31;
    const int hh  = (gid >> 5) & 7;
    const int b   = gid >> 8;

    const float* Qg = g_q + ((size_t)(b * S_ + qt * QT)) * E_ + hh * D_;
    const float* Kg = g_k + ((size_t)b * S_) * E_ + hh * D_;
    const float* Vg = g_v + ((size_t)b * S_) * E_ + hh * D_;
    float*       Og = g_o + ((size_t)(b * S_ + qt * QT)) * E_ + hh * D_;

    // ---- load Q tile transposed: Qs[dd][qi] (one float4 per thread) ----
    {
        int qi  = t >> 4;
        int dd0 = (t & 15) * 4;
        float4 v = *(const float4*)(Qg + (size_t)qi * E_ + dd0);
        Qs[(dd0 + 0) * 32 + qi] = v.x;
        Qs[(dd0 + 1) * 32 + qi] = v.y;
        Qs[(dd0 + 2) * 32 + qi] = v.z;
        Qs[(dd0 + 3) * 32 + qi] = v.w;
    }

    // ---- scores: S[32][1024] = (Q K^T) * scale, K chunks of 256 ----
    const float scale = 0.125f;
    const int qi0 = (t >> 6) * 4;      // 8 q-groups of 4 (uniform within warp)
    const int kj0 = (t & 63) * 4;      // 64 k-groups of 4
    const int kc4 = (t & 63);          // = kj0>>2, chunk column index

    for (int kc = 0; kc < S_; kc += 256) {
        // load + transpose K chunk with XOR swizzle on 16B chunks
#pragma unroll
        for (int i = 0; i < 8; ++i) {
            int idx = t + i * 512;              // 0..4095
            int kj  = idx >> 4;                 // 0..255
            int dd0 = (idx & 15) * 4;
            float4 v = *(const float4*)(Kg + (size_t)(kc + kj) * E_ + dd0);
            int cj = kj >> 2, cr = kj & 3;
            float vv[4] = {v.x, v.y, v.z, v.w};
#pragma unroll
            for (int j = 0; j < 4; ++j) {
                int dd = dd0 + j;
                int cw = cj ^ ((dd >> 2) & 15);
                Kb[dd * 256 + cw * 4 + cr] = vv[j];
            }
        }
        __syncthreads();

        float acc[4][4];
#pragma unroll
        for (int i = 0; i < 4; ++i)
#pragma unroll
            for (int j = 0; j < 4; ++j) acc[i][j] = 0.f;

#pragma unroll 8
        for (int dd = 0; dd < 64; ++dd) {
            float4 qv = *(const float4*)&Qs[dd * 32 + qi0];
            int cw = kc4 ^ ((dd >> 2) & 15);
            float4 kv = *(const float4*)&Kb[dd * 256 + cw * 4];
            float qa[4] = {qv.x, qv.y, qv.z, qv.w};
            float kb[4] = {kv.x, kv.y, kv.z, kv.w};
#pragma unroll
            for (int i = 0; i < 4; ++i)
#pragma unroll
                for (int j = 0; j < 4; ++j)
                    acc[i][j] += qa[i] * kb[j];
        }
#pragma unroll
        for (int i = 0; i < 4; ++i) {
            float4 o = make_float4(acc[i][0] * scale, acc[i][1] * scale,
                                   acc[i][2] * scale, acc[i][3] * scale);
            *(float4*)&Ssc[(size_t)(qi0 + i) * 1024 + kc + kj0] = o;
        }
        __syncthreads();
    }

    // ---- exact top-k + softmax: warp w owns queries 2w, 2w+1 ----
    {
        const int w    = t >> 5;
        const int lane = t & 31;
#pragma unroll
        for (int qq = 0; qq < 2; ++qq) {
            const int qi = w * 2 + qq;
            const float* row = Ssc + (size_t)qi * 1024;

            unsigned u[32];
            unsigned umax = 0u, umin = 0xFFFFFFFFu;
#pragma unroll
            for (int i = 0; i < 32; ++i) {
                u[i] = fmap(row[lane + 32 * i]);
                umax = max(umax, u[i]);
                umin = min(umin, u[i]);
            }
#pragma unroll
            for (int off = 16; off > 0; off >>= 1) {
                umax = max(umax, __shfl_xor_sync(0xFFFFFFFFu, umax, off));
                umin = min(umin, __shfl_xor_sync(0xFFFFFFFFu, umin, off));
            }

            // binary search: largest thr with count(>= thr) >= KTOP
            unsigned lo = umin, hi = umax;
            while (lo < hi) {
                unsigned mid = lo + ((hi - lo + 1) >> 1);
                int c = 0;
#pragma unroll
                for (int i = 0; i < 32; ++i) c += (u[i] >= mid);
#pragma unroll
                for (int off = 16; off > 0; off >>= 1)
                    c += __shfl_xor_sync(0xFFFFFFFFu, c, off);
                if (c >= KTOP) lo = mid; else hi = mid - 1;
            }
            const unsigned thr = lo;
            const float mf = unfmap(umax);

            float sum = 0.f;
#pragma unroll
            for (int i = 0; i < 32; ++i) {
                float ev = 0.f;
                if (u[i] >= thr) ev = __expf(unfmap(u[i]) - mf);
                u[i] = __float_as_uint(ev);
                sum += ev;
            }
#pragma unroll
            for (int off = 16; off > 0; off >>= 1)
                sum += __shfl_xor_sync(0xFFFFFFFFu, sum, off);
            const float inv = 1.f / sum;

            float* wrow = Ssc + (size_t)qi * 1024;
#pragma unroll
            for (int i = 0; i < 32; ++i)
                wrow[lane + 32 * i] = __uint_as_float(u[i]) * inv;
        }
    }
    __syncthreads();

    // ---- PV: O[32][64] = P @ V ; thread = (js, qg, dg) ; 4q x 4d x j-stripe ----
    {
        const int js   = t >> 7;            // 0..3 j-stripe
        const int slot = t & 127;
        const int pq0  = (slot >> 4) * 4;   // query base
        const int pd0  = (slot & 15) * 4;   // d base
        const int jb   = js * 64;
        float* Vb = Kb;                     // [256][64]

        float acc[4][4];
#pragma unroll
        for (int i = 0; i < 4; ++i)
#pragma unroll
            for (int c = 0; c < 4; ++c) acc[i][c] = 0.f;

        for (int vc = 0; vc < S_; vc += 256) {
#pragma unroll
            for (int i = 0; i < 8; ++i) {
                int idx = t + i * 512;
                int kj  = idx >> 4;
                int d0  = (idx & 15) * 4;
                *(float4*)&Vb[kj * 64 + d0] =
                    *(const float4*)(Vg + (size_t)(vc + kj) * E_ + d0);
            }
            __syncthreads();

#pragma unroll 2
            for (int jj = 0; jj < 64; jj += 4) {
                float pa[4][4], va[4][4];
#pragma unroll
                for (int i = 0; i < 4; ++i)
                    *(float4*)pa[i] = *(const float4*)&Ssc[(size_t)(pq0 + i) * 1024 + vc + jb + jj];
#pragma unroll
                for (int r = 0; r < 4; ++r)
                    *(float4*)va[r] = *(const float4*)&Vb[(jb + jj + r) * 64 + pd0];
#pragma unroll
                for (int i = 0; i < 4; ++i)
#pragma unroll
                    for (int r = 0; r < 4; ++r)
#pragma unroll
                        for (int c = 0; c < 4; ++c)
                            acc[i][c] += pa[i][r] * va[r][c];
            }
            __syncthreads();
        }

        // reduce 4 j-stripes via smem (reuse Kb region)
        float* red = Kb;                    // 4*128*16 = 8192 floats
#pragma unroll
        for (int i = 0; i < 4; ++i)
            *(float4*)&red[((js * 128 + slot) * 16) + i * 4] =
                make_float4(acc[i][0], acc[i][1], acc[i][2], acc[i][3]);
        __syncthreads();

#pragma unroll
        for (int k = 0; k < 4; ++k) {
            int m  = t + k * 512;           // 0..2047
            int qi = m >> 6, dd = m & 63;
            int sl = (qi >> 2) * 16 + (dd >> 2);
            int e  = (qi & 3) * 4 + (dd & 3);
            float vsum = red[(0 * 128 + sl) * 16 + e] + red[(1 * 128 + sl) * 16 + e]
                       + red[(2 * 128 + sl) * 16 + e] + red[(3 * 128 + sl) * 16 + e];
            Og[(size_t)qi * E_ + dd] = vsum;
        }
    }
}

// ======================================================================
// mean pool over S, then final FC
// ======================================================================
__global__ void meanpool_k(const float* __restrict__ h, float* __restrict__ pool)
{
    __shared__ float red[512];
    const int b = blockIdx.y;
    const int e = blockIdx.x * 128 + (threadIdx.x & 127);
    const int slice = threadIdx.x >> 7;
    const float* base = h + (size_t)b * S_ * E_ + e;
    float s = 0.f;
#pragma unroll 8
    for (int i = 0; i < 256; ++i)
        s += base[(size_t)(slice * 256 + i) * E_];
    red[threadIdx.x] = s;
    __syncthreads();
    if (slice == 0) {
        float tot = red[threadIdx.x] + red[threadIdx.x + 128] +
                    red[threadIdx.x + 256] + red[threadIdx.x + 384];
        pool[b * E_ + e] = tot * (1.f / (float)S_);
    }
}

__global__ void fc_k(const float* __restrict__ pool, const float* __restrict__ w,
                     const float* __restrict__ bias, float* __restrict__ out)
{
    int t = threadIdx.x;
    if (t >= B_ * NCLS) return;
    int b = t / NCLS, c = t % NCLS;
    float s = bias[c];
    const float* p = pool + b * E_;
#pragma unroll 8
    for (int k = 0; k < E_; ++k)
        s += p[k] * w[k * NCLS + c];
    out[t] = s;
}

// ======================================================================
// launch
// ======================================================================
extern "C" void kernel_launch(void* const* d_in, const int* in_sizes, int n_in,
                              void* d_out, int out_size)
{
    (void)in_sizes; (void)n_in; (void)out_size;

    const float* x     = (const float*)d_in[0];
    const float* emb_w = (const float*)d_in[1];
    const float* emb_b = (const float*)d_in[2];
    const float* Wq    = (const float*)d_in[3];
    const float* Wk    = (const float*)d_in[4];
    const float* Wv    = (const float*)d_in[5];
    const float* Wo    = (const float*)d_in[6];
    const float* bq    = (const float*)d_in[7];
    const float* bk    = (const float*)d_in[8];
    const float* bv    = (const float*)d_in[9];
    const float* bo    = (const float*)d_in[10];
    const float* fc_w  = (const float*)d_in[11];
    const float* fc_b  = (const float*)d_in[12];
    float* out = (float*)d_out;

    float *h, *q, *k, *v, *o, *pool;
    cudaGetSymbolAddress((void**)&h,    g_h);
    cudaGetSymbolAddress((void**)&q,    g_q);
    cudaGetSymbolAddress((void**)&k,    g_k);
    cudaGetSymbolAddress((void**)&v,    g_v);
    cudaGetSymbolAddress((void**)&o,    g_o);
    cudaGetSymbolAddress((void**)&pool, g_pool);

    cudaFuncSetAttribute(attn_kernel, cudaFuncAttributeMaxDynamicSharedMemorySize, SMEM_BYTES);

    const int M = B_ * S_;                          // 8192
    dim3 ggrid(E_ / BN, M / BM);                    // (4, 64)
    dim3 qkvgrid(E_ / BN, M / BM, 3);               // (4, 64, 3)

    sgemm_bias<<<ggrid, 256>>>(x, emb_w, emb_b, h, M, FIN, E_);

    for (int l = 0; l < L_; ++l) {
        const size_t wo  = (size_t)l * E_ * E_;
        const size_t bo_ = (size_t)l * E_;
        sgemm_qkv<<<qkvgrid, 256>>>(h, Wq + wo, Wk + wo, Wv + wo,
                                    bq + bo_, bk + bo_, bv + bo_, q, k, v);
        attn_kernel<<<B_ * H_ * (S_ / QT), 512, SMEM_BYTES>>>();
        sgemm_bias<<<ggrid, 256>>>(o, Wo + wo, bo + bo_, h, M, E_, E_);
    }

    meanpool_k<<<dim3(E_ / 128, B_), 512>>>(h, pool);
    fc_k<<<1, 128>>>(pool, fc_w, fc_b, out);
}

// round 4
// speedup vs baseline: 1.6125x; 1.2547x over previous
#include <cuda_runtime.h>
#include <math.h>

// ---------------- problem constants ----------------
#define B_   8
#define S_   1024
#define E_   512
#define H_   8
#define D_   64
#define L_   4
#define KTOP 256
#define FIN  128
#define NCLS 10
#define QT   32

// ---------------- device scratch ----------------
__device__ float g_h[(size_t)B_ * S_ * E_];
__device__ float g_q[(size_t)B_ * S_ * E_];
__device__ float g_k[(size_t)B_ * S_ * E_];
__device__ float g_v[(size_t)B_ * S_ * E_];
__device__ float g_o[(size_t)B_ * S_ * E_];
__device__ float g_pool[B_ * E_];

// ---------------- helpers ----------------
__device__ __forceinline__ float tf32f(float x) {
    unsigned u;
    asm("cvt.rna.tf32.f32 %0, %1;" : "=r"(u) : "f"(x));
    return __uint_as_float(u);
}
__device__ __forceinline__ void mma_tf32(float c[4],
    unsigned a0, unsigned a1, unsigned a2, unsigned a3,
    unsigned b0, unsigned b1)
{
    asm volatile(
        "mma.sync.aligned.m16n8k8.row.col.f32.tf32.tf32.f32 "
        "{%0,%1,%2,%3},{%4,%5,%6,%7},{%8,%9},{%0,%1,%2,%3};"
        : "+f"(c[0]), "+f"(c[1]), "+f"(c[2]), "+f"(c[3])
        : "r"(a0), "r"(a1), "r"(a2), "r"(a3), "r"(b0), "r"(b1));
}
__device__ __forceinline__ unsigned fu(float x) { return __float_as_uint(x); }

__device__ __forceinline__ unsigned fmap(float x) {
    unsigned u = __float_as_uint(x);
    return (u & 0x80000000u) ? ~u : (u | 0x80000000u);
}
__device__ __forceinline__ float unfmap(unsigned u) {
    return (u & 0x80000000u) ? __uint_as_float(u & 0x7FFFFFFFu)
                             : __uint_as_float(~u);
}
// split x into tf32 hi/lo
__device__ __forceinline__ void split2(float x, float& h, float& l) {
    h = tf32f(x);
    l = tf32f(x - h);
}

// ======================================================================
// split-tf32 GEMM: C[M,N] = A[M,K] @ W[K,N] + bias[N]
// 128x128 tile, BK=32, 256 threads = 8 warps (2m x 4n), warp tile 64x32.
// hi/lo smem planes, 3 MMAs per fragment pair.
// ======================================================================
#define GA 36
#define GB 136
#define GEMM_SMEM ((128*GA*2 + 32*GB*2) * 4)   // 71680 bytes

__device__ __forceinline__
void gemm_body(const float* __restrict__ A, const float* __restrict__ W,
               const float* __restrict__ bias, float* __restrict__ C,
               int M, int K, int N)
{
    extern __shared__ float gsm[];
    float* Ash = gsm;                    // [128][GA]
    float* Asl = Ash + 128 * GA;
    float* Bsh = Asl + 128 * GA;         // [32][GB]
    float* Bsl = Bsh + 32 * GB;

    const int t    = threadIdx.x;
    const int m0   = blockIdx.y * 128;
    const int n0   = blockIdx.x * 128;
    const int w    = t >> 5;
    const int lane = t & 31;
    const int wm   = w >> 2;
    const int wn   = w & 3;
    const int grp  = lane >> 2;
    const int tg   = lane & 3;

    float acc[4][4][4];
#pragma unroll
    for (int i = 0; i < 4; ++i)
#pragma unroll
        for (int j = 0; j < 4; ++j)
#pragma unroll
            for (int c = 0; c < 4; ++c) acc[i][j][c] = 0.f;

    const float* Aptr = A + (size_t)m0 * K;
    const float* Wptr = W + n0;

    for (int k0 = 0; k0 < K; k0 += 32) {
#pragma unroll
        for (int i = 0; i < 4; ++i) {
            int idx = t + i * 256;
            int row = idx >> 3;
            int c4  = (idx & 7) * 4;
            float4 v = *(const float4*)(Aptr + (size_t)row * K + k0 + c4);
            float h0, l0, h1, l1, h2, l2, h3, l3;
            split2(v.x, h0, l0); split2(v.y, h1, l1);
            split2(v.z, h2, l2); split2(v.w, h3, l3);
            *(float4*)&Ash[row * GA + c4] = make_float4(h0, h1, h2, h3);
            *(float4*)&Asl[row * GA + c4] = make_float4(l0, l1, l2, l3);
        }
#pragma unroll
        for (int i = 0; i < 4; ++i) {
            int idx = t + i * 256;
            int row = idx >> 5;
            int c4  = (idx & 31) * 4;
            float4 v = *(const float4*)(Wptr + (size_t)(k0 + row) * N + c4);
            float h0, l0, h1, l1, h2, l2, h3, l3;
            split2(v.x, h0, l0); split2(v.y, h1, l1);
            split2(v.z, h2, l2); split2(v.w, h3, l3);
            *(float4*)&Bsh[row * GB + c4] = make_float4(h0, h1, h2, h3);
            *(float4*)&Bsl[row * GB + c4] = make_float4(l0, l1, l2, l3);
        }
        __syncthreads();

#pragma unroll
        for (int ks = 0; ks < 4; ++ks) {
            const int ka = ks * 8 + tg;
            unsigned bh[4][2], bl[4][2];
#pragma unroll
            for (int nt = 0; nt < 4; ++nt) {
                int c = wn * 32 + nt * 8 + grp;
                bh[nt][0] = fu(Bsh[ka * GB + c]);
                bh[nt][1] = fu(Bsh[(ka + 4) * GB + c]);
                bl[nt][0] = fu(Bsl[ka * GB + c]);
                bl[nt][1] = fu(Bsl[(ka + 4) * GB + c]);
            }
#pragma unroll
            for (int mt = 0; mt < 4; ++mt) {
                int r = wm * 64 + mt * 16 + grp;
                unsigned ah0 = fu(Ash[r * GA + ka]);
                unsigned ah1 = fu(Ash[(r + 8) * GA + ka]);
                unsigned ah2 = fu(Ash[r * GA + ka + 4]);
                unsigned ah3 = fu(Ash[(r + 8) * GA + ka + 4]);
                unsigned al0 = fu(Asl[r * GA + ka]);
                unsigned al1 = fu(Asl[(r + 8) * GA + ka]);
                unsigned al2 = fu(Asl[r * GA + ka + 4]);
                unsigned al3 = fu(Asl[(r + 8) * GA + ka + 4]);
#pragma unroll
                for (int nt = 0; nt < 4; ++nt) {
                    mma_tf32(acc[mt][nt], ah0, ah1, ah2, ah3, bh[nt][0], bh[nt][1]);
                    mma_tf32(acc[mt][nt], ah0, ah1, ah2, ah3, bl[nt][0], bl[nt][1]);
                    mma_tf32(acc[mt][nt], al0, al1, al2, al3, bh[nt][0], bh[nt][1]);
                }
            }
        }
        __syncthreads();
    }

#pragma unroll
    for (int nt = 0; nt < 4; ++nt) {
        const int c = n0 + wn * 32 + nt * 8 + 2 * tg;
        float2 bv = *(const float2*)&bias[c];
#pragma unroll
        for (int mt = 0; mt < 4; ++mt) {
            int r = m0 + wm * 64 + mt * 16 + grp;
            float2 r0 = make_float2(acc[mt][nt][0] + bv.x, acc[mt][nt][1] + bv.y);
            float2 r1 = make_float2(acc[mt][nt][2] + bv.x, acc[mt][nt][3] + bv.y);
            *(float2*)&C[(size_t)r * N + c]       = r0;
            *(float2*)&C[(size_t)(r + 8) * N + c] = r1;
        }
    }
}

__global__ __launch_bounds__(256, 2)
void gemm_tf32(const float* __restrict__ A, const float* __restrict__ W,
               const float* __restrict__ bias, float* __restrict__ C,
               int M, int K, int N)
{
    gemm_body(A, W, bias, C, M, K, N);
}

__global__ __launch_bounds__(256, 2)
void gemm_qkv(const float* __restrict__ A,
              const float* __restrict__ Wq, const float* __restrict__ Wk,
              const float* __restrict__ Wv,
              const float* __restrict__ bq, const float* __restrict__ bk,
              const float* __restrict__ bv,
              float* __restrict__ q, float* __restrict__ k, float* __restrict__ v)
{
    const float* W; const float* bb; float* C;
    if (blockIdx.z == 0)      { W = Wq; bb = bq; C = q; }
    else if (blockIdx.z == 1) { W = Wk; bb = bk; C = k; }
    else                      { W = Wv; bb = bv; C = v; }
    gemm_body(A, W, bb, C, B_ * S_, E_, E_);
}

// ======================================================================
// Sparse attention v4 (split-tf32 tensor cores)
//  one CTA per (b,h,32-query tile), 512 threads = 16 warps.
//  scores: S[q][key] row-major (stride SP=1028), split-tf32 mma
//  top-k:  exact per-query binary search (fp32-accurate scores)
//  PV:     O = P V via split-tf32 mma, P/V split in registers
// ======================================================================
#define SP   1028              // St row stride (== 4 mod 32)
#define QSP  40
#define KVP  72

#define ST_F (32 * SP)         // 32896
#define QS_F (64 * QSP)        //  2560
#define KV_F (256 * KVP)       // 18432
#define ATTN_SMEM ((ST_F + 2 * QS_F + KV_F) * 4)   // 225792 bytes

__global__ __launch_bounds__(512, 1)
void attn_kernel()
{
    extern __shared__ float sm[];
    float* St  = sm;                    // [32][SP]   scores then P (fp32)
    float* Qsh = sm + ST_F;             // [64][QSP]  Q^T hi (prescaled)
    float* Qsl = Qsh + QS_F;            // [64][QSP]  Q^T lo
    float* KV  = Qsl + QS_F;            // [256][KVP] K/V raw fp32; later red

    const int t    = threadIdx.x;
    const int w    = t >> 5;
    const int lane = t & 31;
    const int grp  = lane >> 2;
    const int tg   = lane & 3;

    const int gid = blockIdx.x;
    const int qt  = gid & 31;
    const int hh  = (gid >> 5) & 7;
    const int b   = gid >> 8;

    const float* Qg = g_q + ((size_t)(b * S_ + qt * QT)) * E_ + hh * D_;
    const float* Kg = g_k + ((size_t)b * S_) * E_ + hh * D_;
    const float* Vg = g_v + ((size_t)b * S_) * E_ + hh * D_;
    float*       Og = g_o + ((size_t)(b * S_ + qt * QT)) * E_ + hh * D_;

    // ---- phase 0: Q^T (prescaled by 1/8) split into hi/lo planes ----
    {
        int qi  = t & 31;
        int dd0 = (t >> 5) * 4;
        float4 v = *(const float4*)(Qg + (size_t)qi * E_ + dd0);
        float h, l;
        split2(v.x * 0.125f, h, l); Qsh[(dd0+0)*QSP+qi] = h; Qsl[(dd0+0)*QSP+qi] = l;
        split2(v.y * 0.125f, h, l); Qsh[(dd0+1)*QSP+qi] = h; Qsl[(dd0+1)*QSP+qi] = l;
        split2(v.z * 0.125f, h, l); Qsh[(dd0+2)*QSP+qi] = h; Qsl[(dd0+2)*QSP+qi] = l;
        split2(v.w * 0.125f, h, l); Qsh[(dd0+3)*QSP+qi] = h; Qsl[(dd0+3)*QSP+qi] = l;
    }
    __syncthreads();

    // ---- phase 1: scores S[q][key] = (K Q^T)^T, K chunks of 256 ----
    for (int kc = 0; kc < S_; kc += 256) {
#pragma unroll
        for (int i = 0; i < 8; ++i) {
            int idx = t + i * 512;
            int kj  = idx >> 4;
            int dd0 = (idx & 15) * 4;
            *(float4*)&KV[kj * KVP + dd0] =
                *(const float4*)(Kg + (size_t)(kc + kj) * E_ + dd0);
        }
        __syncthreads();

        float acc[4][4];
#pragma unroll
        for (int nt = 0; nt < 4; ++nt)
#pragma unroll
            for (int c = 0; c < 4; ++c) acc[nt][c] = 0.f;

        const int rbase = w * 16 + grp;
#pragma unroll
        for (int ks = 0; ks < 8; ++ks) {
            const int ka = ks * 8 + tg;
            float x0 = KV[rbase * KVP + ka];
            float x1 = KV[(rbase + 8) * KVP + ka];
            float x2 = KV[rbase * KVP + ka + 4];
            float x3 = KV[(rbase + 8) * KVP + ka + 4];
            float h0, l0, h1, l1, h2, l2, h3, l3;
            split2(x0, h0, l0); split2(x1, h1, l1);
            split2(x2, h2, l2); split2(x3, h3, l3);
            unsigned ah0 = fu(h0), ah1 = fu(h1), ah2 = fu(h2), ah3 = fu(h3);
            unsigned al0 = fu(l0), al1 = fu(l1), al2 = fu(l2), al3 = fu(l3);
#pragma unroll
            for (int nt = 0; nt < 4; ++nt) {
                const int qcol = nt * 8 + grp;
                unsigned bh0 = fu(Qsh[ka * QSP + qcol]);
                unsigned bh1 = fu(Qsh[(ka + 4) * QSP + qcol]);
                unsigned bl0 = fu(Qsl[ka * QSP + qcol]);
                unsigned bl1 = fu(Qsl[(ka + 4) * QSP + qcol]);
                mma_tf32(acc[nt], ah0, ah1, ah2, ah3, bh0, bh1);
                mma_tf32(acc[nt], ah0, ah1, ah2, ah3, bl0, bl1);
                mma_tf32(acc[nt], al0, al1, al2, al3, bh0, bh1);
            }
        }
        const int key = kc + w * 16 + grp;
#pragma unroll
        for (int nt = 0; nt < 4; ++nt) {
            const int q = nt * 8 + 2 * tg;
            St[q * SP + key]           = acc[nt][0];
            St[(q + 1) * SP + key]     = acc[nt][1];
            St[q * SP + key + 8]       = acc[nt][2];
            St[(q + 1) * SP + key + 8] = acc[nt][3];
        }
        __syncthreads();
    }

    // ---- phase 2: exact top-k + softmax; warp w owns queries 2w, 2w+1 ----
#pragma unroll
    for (int qq = 0; qq < 2; ++qq) {
        const int qi = w * 2 + qq;
        float* row = St + (size_t)qi * SP;

        unsigned u[32];
        unsigned umax = 0u, umin = 0xFFFFFFFFu;
#pragma unroll
        for (int i = 0; i < 32; ++i) {
            u[i] = fmap(row[lane + 32 * i]);
            umax = max(umax, u[i]);
            umin = min(umin, u[i]);
        }
#pragma unroll
        for (int off = 16; off > 0; off >>= 1) {
            umax = max(umax, __shfl_xor_sync(0xFFFFFFFFu, umax, off));
            umin = min(umin, __shfl_xor_sync(0xFFFFFFFFu, umin, off));
        }

        unsigned lo = umin, hi = umax;
        while (lo < hi) {
            unsigned mid = lo + ((hi - lo + 1) >> 1);
            int c = 0;
#pragma unroll
            for (int i = 0; i < 32; ++i) c += (u[i] >= mid);
#pragma unroll
            for (int off = 16; off > 0; off >>= 1)
                c += __shfl_xor_sync(0xFFFFFFFFu, c, off);
            if (c >= KTOP) lo = mid; else hi = mid - 1;
        }
        const unsigned thr = lo;
        const float mf = unfmap(umax);

        float sum = 0.f;
#pragma unroll
        for (int i = 0; i < 32; ++i) {
            float ev = 0.f;
            if (u[i] >= thr) ev = __expf(unfmap(u[i]) - mf);
            u[i] = __float_as_uint(ev);
            sum += ev;
        }
#pragma unroll
        for (int off = 16; off > 0; off >>= 1)
            sum += __shfl_xor_sync(0xFFFFFFFFu, sum, off);
        const float inv = 1.f / sum;

#pragma unroll
        for (int i = 0; i < 32; ++i)
            row[lane + 32 * i] = __uint_as_float(u[i]) * inv;
    }
    __syncthreads();

    // ---- phase 3: O = P V ; warp = (kg key-quarter, wn d-slice) ----
    {
        const int kg = w >> 2;
        const int wn = w & 3;

        float acc[2][2][4];
#pragma unroll
        for (int mt = 0; mt < 2; ++mt)
#pragma unroll
            for (int nt = 0; nt < 2; ++nt)
#pragma unroll
                for (int c = 0; c < 4; ++c) acc[mt][nt][c] = 0.f;

        for (int kc = 0; kc < S_; kc += 256) {
#pragma unroll
            for (int i = 0; i < 8; ++i) {
                int idx = t + i * 512;
                int kj  = idx >> 4;
                int dd0 = (idx & 15) * 4;
                *(float4*)&KV[kj * KVP + dd0] =
                    *(const float4*)(Vg + (size_t)(kc + kj) * E_ + dd0);
            }
            __syncthreads();

#pragma unroll
            for (int ks = 0; ks < 8; ++ks) {
                const int kl = kg * 64 + ks * 8;
                const int k0 = kc + kl;

                unsigned bh[2][2], bl[2][2];
#pragma unroll
                for (int nt = 0; nt < 2; ++nt) {
                    const int col = wn * 16 + nt * 8 + grp;
                    float y0 = KV[(kl + tg) * KVP + col];
                    float y1 = KV[(kl + tg + 4) * KVP + col];
                    float h0, l0, h1, l1;
                    split2(y0, h0, l0); split2(y1, h1, l1);
                    bh[nt][0] = fu(h0); bh[nt][1] = fu(h1);
                    bl[nt][0] = fu(l0); bl[nt][1] = fu(l1);
                }
#pragma unroll
                for (int mt = 0; mt < 2; ++mt) {
                    float p0 = St[(mt * 16 + grp) * SP + k0 + tg];
                    float p1 = St[(mt * 16 + grp + 8) * SP + k0 + tg];
                    float p2 = St[(mt * 16 + grp) * SP + k0 + tg + 4];
                    float p3 = St[(mt * 16 + grp + 8) * SP + k0 + tg + 4];
                    float h0, l0, h1, l1, h2, l2, h3, l3;
                    split2(p0, h0, l0); split2(p1, h1, l1);
                    split2(p2, h2, l2); split2(p3, h3, l3);
                    unsigned ah0 = fu(h0), ah1 = fu(h1), ah2 = fu(h2), ah3 = fu(h3);
                    unsigned al0 = fu(l0), al1 = fu(l1), al2 = fu(l2), al3 = fu(l3);
#pragma unroll
                    for (int nt = 0; nt < 2; ++nt) {
                        mma_tf32(acc[mt][nt], ah0, ah1, ah2, ah3, bh[nt][0], bh[nt][1]);
                        mma_tf32(acc[mt][nt], ah0, ah1, ah2, ah3, bl[nt][0], bl[nt][1]);
                        mma_tf32(acc[mt][nt], al0, al1, al2, al3, bh[nt][0], bh[nt][1]);
                    }
                }
            }
            __syncthreads();
        }

        // reduce 4 key-quarters via smem (reuse KV region)
        float* red = KV;                              // [4][32][68]
#pragma unroll
        for (int mt = 0; mt < 2; ++mt)
#pragma unroll
            for (int nt = 0; nt < 2; ++nt) {
                const int q = mt * 16 + grp;
                const int d = wn * 16 + nt * 8 + 2 * tg;
                *(float2*)&red[kg * 2176 + q * 68 + d] =
                    make_float2(acc[mt][nt][0], acc[mt][nt][1]);
                *(float2*)&red[kg * 2176 + (q + 8) * 68 + d] =
                    make_float2(acc[mt][nt][2], acc[mt][nt][3]);
            }
        __syncthreads();

#pragma unroll
        for (int kk = 0; kk < 4; ++kk) {
            int m  = t + kk * 512;
            int qi = m >> 6, dd = m & 63;
            float s = red[0 * 2176 + qi * 68 + dd] + red[1 * 2176 + qi * 68 + dd]
                    + red[2 * 2176 + qi * 68 + dd] + red[3 * 2176 + qi * 68 + dd];
            Og[(size_t)qi * E_ + dd] = s;
        }
    }
}

// ======================================================================
// mean pool + final FC
// ======================================================================
__global__ void meanpool_k(const float* __restrict__ h, float* __restrict__ pool)
{
    __shared__ float red[512];
    const int b = blockIdx.y;
    const int e = blockIdx.x * 128 + (threadIdx.x & 127);
    const int slice = threadIdx.x >> 7;
    const float* base = h + (size_t)b * S_ * E_ + e;
    float s = 0.f;
#pragma unroll 8
    for (int i = 0; i < 256; ++i)
        s += base[(size_t)(slice * 256 + i) * E_];
    red[threadIdx.x] = s;
    __syncthreads();
    if (slice == 0) {
        float tot = red[threadIdx.x] + red[threadIdx.x + 128] +
                    red[threadIdx.x + 256] + red[threadIdx.x + 384];
        pool[b * E_ + e] = tot * (1.f / (float)S_);
    }
}

__global__ void fc_k(const float* __restrict__ pool, const float* __restrict__ w,
                     const float* __restrict__ bias, float* __restrict__ out)
{
    int t = threadIdx.x;
    if (t >= B_ * NCLS) return;
    int b = t / NCLS, c = t % NCLS;
    float s = bias[c];
    const float* p = pool + b * E_;
#pragma unroll 8
    for (int k = 0; k < E_; ++k)
        s += p[k] * w[k * NCLS + c];
    out[t] = s;
}

// ======================================================================
// launch
// ======================================================================
extern "C" void kernel_launch(void* const* d_in, const int* in_sizes, int n_in,
                              void* d_out, int out_size)
{
    (void)in_sizes; (void)n_in; (void)out_size;

    const float* x     = (const float*)d_in[0];
    const float* emb_w = (const float*)d_in[1];
    const float* emb_b = (const float*)d_in[2];
    const float* Wq    = (const float*)d_in[3];
    const float* Wk    = (const float*)d_in[4];
    const float* Wv    = (const float*)d_in[5];
    const float* Wo    = (const float*)d_in[6];
    const float* bq    = (const float*)d_in[7];
    const float* bk    = (const float*)d_in[8];
    const float* bv    = (const float*)d_in[9];
    const float* bo    = (const float*)d_in[10];
    const float* fc_w  = (const float*)d_in[11];
    const float* fc_b  = (const float*)d_in[12];
    float* out = (float*)d_out;

    float *h, *q, *k, *v, *o, *pool;
    cudaGetSymbolAddress((void**)&h,    g_h);
    cudaGetSymbolAddress((void**)&q,    g_q);
    cudaGetSymbolAddress((void**)&k,    g_k);
    cudaGetSymbolAddress((void**)&v,    g_v);
    cudaGetSymbolAddress((void**)&o,    g_o);
    cudaGetSymbolAddress((void**)&pool, g_pool);

    cudaFuncSetAttribute(attn_kernel, cudaFuncAttributeMaxDynamicSharedMemorySize, ATTN_SMEM);
    cudaFuncSetAttribute(gemm_tf32,   cudaFuncAttributeMaxDynamicSharedMemorySize, GEMM_SMEM);
    cudaFuncSetAttribute(gemm_qkv,    cudaFuncAttributeMaxDynamicSharedMemorySize, GEMM_SMEM);

    const int M = B_ * S_;                          // 8192
    dim3 ggrid(E_ / 128, M / 128);                  // (4, 64)
    dim3 qkvgrid(E_ / 128, M / 128, 3);

    gemm_tf32<<<ggrid, 256, GEMM_SMEM>>>(x, emb_w, emb_b, h, M, FIN, E_);

    for (int l = 0; l < L_; ++l) {
        const size_t wo  = (size_t)l * E_ * E_;
        const size_t bo_ = (size_t)l * E_;
        gemm_qkv<<<qkvgrid, 256, GEMM_SMEM>>>(h, Wq + wo, Wk + wo, Wv + wo,
                                              bq + bo_, bk + bo_, bv + bo_, q, k, v);
        attn_kernel<<<B_ * H_ * (S_ / QT), 512, ATTN_SMEM>>>();
        gemm_tf32<<<ggrid, 256, GEMM_SMEM>>>(o, Wo + wo, bo + bo_, h, M, E_, E_);
    }

    meanpool_k<<<dim3(E_ / 128, B_), 512>>>(h, pool);
    fc_k<<<1, 128>>>(pool, fc_w, fc_b, out);
}

// round 5
// speedup vs baseline: 1.6238x; 1.0070x over previous
#include <cuda_runtime.h>
#include <math.h>

// ---------------- problem constants ----------------
#define B_   8
#define S_   1024
#define E_   512
#define H_   8
#define D_   64
#define L_   4
#define KTOP 256
#define FIN  128
#define NCLS 10
#define QT   32

// ---------------- device scratch ----------------
__device__ float g_h[(size_t)B_ * S_ * E_];
__device__ float g_q[(size_t)B_ * S_ * E_];
__device__ float g_k[(size_t)B_ * S_ * E_];
__device__ float g_v[(size_t)B_ * S_ * E_];
__device__ float g_o[(size_t)B_ * S_ * E_];
__device__ float g_pool[B_ * E_];

// ---------------- helpers ----------------
__device__ __forceinline__ float tf32f(float x) {
    unsigned u;
    asm("cvt.rna.tf32.f32 %0, %1;" : "=r"(u) : "f"(x));
    return __uint_as_float(u);
}
__device__ __forceinline__ void mma_tf32(float c[4],
    unsigned a0, unsigned a1, unsigned a2, unsigned a3,
    unsigned b0, unsigned b1)
{
    asm volatile(
        "mma.sync.aligned.m16n8k8.row.col.f32.tf32.tf32.f32 "
        "{%0,%1,%2,%3},{%4,%5,%6,%7},{%8,%9},{%0,%1,%2,%3};"
        : "+f"(c[0]), "+f"(c[1]), "+f"(c[2]), "+f"(c[3])
        : "r"(a0), "r"(a1), "r"(a2), "r"(a3), "r"(b0), "r"(b1));
}
__device__ __forceinline__ unsigned fu(float x) { return __float_as_uint(x); }

__device__ __forceinline__ unsigned fmap(float x) {
    unsigned u = __float_as_uint(x);
    return (u & 0x80000000u) ? ~u : (u | 0x80000000u);
}
__device__ __forceinline__ float unfmap(unsigned u) {
    return (u & 0x80000000u) ? __uint_as_float(u & 0x7FFFFFFFu)
                             : __uint_as_float(~u);
}
__device__ __forceinline__ void split2(float x, float& h, float& l) {
    h = tf32f(x);
    l = tf32f(x - h);
}

// ======================================================================
// split-tf32 GEMM: C[M,N] = A[M,K] @ W[K,N] + bias[N]
// 128x128 tile, BK=32, 256 threads = 8 warps (2m x 4n), warp tile 64x32.
// ======================================================================
#define GA 36
#define GB 136
#define GEMM_SMEM ((128*GA*2 + 32*GB*2) * 4)   // 71680 bytes

__device__ __forceinline__
void gemm_body(const float* __restrict__ A, const float* __restrict__ W,
               const float* __restrict__ bias, float* __restrict__ C,
               int M, int K, int N)
{
    extern __shared__ float gsm[];
    float* Ash = gsm;
    float* Asl = Ash + 128 * GA;
    float* Bsh = Asl + 128 * GA;
    float* Bsl = Bsh + 32 * GB;

    const int t    = threadIdx.x;
    const int m0   = blockIdx.y * 128;
    const int n0   = blockIdx.x * 128;
    const int w    = t >> 5;
    const int lane = t & 31;
    const int wm   = w >> 2;
    const int wn   = w & 3;
    const int grp  = lane >> 2;
    const int tg   = lane & 3;

    float acc[4][4][4];
#pragma unroll
    for (int i = 0; i < 4; ++i)
#pragma unroll
        for (int j = 0; j < 4; ++j)
#pragma unroll
            for (int c = 0; c < 4; ++c) acc[i][j][c] = 0.f;

    const float* Aptr = A + (size_t)m0 * K;
    const float* Wptr = W + n0;

    for (int k0 = 0; k0 < K; k0 += 32) {
#pragma unroll
        for (int i = 0; i < 4; ++i) {
            int idx = t + i * 256;
            int row = idx >> 3;
            int c4  = (idx & 7) * 4;
            float4 v = *(const float4*)(Aptr + (size_t)row * K + k0 + c4);
            float h0, l0, h1, l1, h2, l2, h3, l3;
            split2(v.x, h0, l0); split2(v.y, h1, l1);
            split2(v.z, h2, l2); split2(v.w, h3, l3);
            *(float4*)&Ash[row * GA + c4] = make_float4(h0, h1, h2, h3);
            *(float4*)&Asl[row * GA + c4] = make_float4(l0, l1, l2, l3);
        }
#pragma unroll
        for (int i = 0; i < 4; ++i) {
            int idx = t + i * 256;
            int row = idx >> 5;
            int c4  = (idx & 31) * 4;
            float4 v = *(const float4*)(Wptr + (size_t)(k0 + row) * N + c4);
            float h0, l0, h1, l1, h2, l2, h3, l3;
            split2(v.x, h0, l0); split2(v.y, h1, l1);
            split2(v.z, h2, l2); split2(v.w, h3, l3);
            *(float4*)&Bsh[row * GB + c4] = make_float4(h0, h1, h2, h3);
            *(float4*)&Bsl[row * GB + c4] = make_float4(l0, l1, l2, l3);
        }
        __syncthreads();

#pragma unroll
        for (int ks = 0; ks < 4; ++ks) {
            const int ka = ks * 8 + tg;
            unsigned bh[4][2], bl[4][2];
#pragma unroll
            for (int nt = 0; nt < 4; ++nt) {
                int c = wn * 32 + nt * 8 + grp;
                bh[nt][0] = fu(Bsh[ka * GB + c]);
                bh[nt][1] = fu(Bsh[(ka + 4) * GB + c]);
                bl[nt][0] = fu(Bsl[ka * GB + c]);
                bl[nt][1] = fu(Bsl[(ka + 4) * GB + c]);
            }
#pragma unroll
            for (int mt = 0; mt < 4; ++mt) {
                int r = wm * 64 + mt * 16 + grp;
                unsigned ah0 = fu(Ash[r * GA + ka]);
                unsigned ah1 = fu(Ash[(r + 8) * GA + ka]);
                unsigned ah2 = fu(Ash[r * GA + ka + 4]);
                unsigned ah3 = fu(Ash[(r + 8) * GA + ka + 4]);
                unsigned al0 = fu(Asl[r * GA + ka]);
                unsigned al1 = fu(Asl[(r + 8) * GA + ka]);
                unsigned al2 = fu(Asl[r * GA + ka + 4]);
                unsigned al3 = fu(Asl[(r + 8) * GA + ka + 4]);
#pragma unroll
                for (int nt = 0; nt < 4; ++nt) {
                    mma_tf32(acc[mt][nt], ah0, ah1, ah2, ah3, bh[nt][0], bh[nt][1]);
                    mma_tf32(acc[mt][nt], ah0, ah1, ah2, ah3, bl[nt][0], bl[nt][1]);
                    mma_tf32(acc[mt][nt], al0, al1, al2, al3, bh[nt][0], bh[nt][1]);
                }
            }
        }
        __syncthreads();
    }

#pragma unroll
    for (int nt = 0; nt < 4; ++nt) {
        const int c = n0 + wn * 32 + nt * 8 + 2 * tg;
        float2 bv = *(const float2*)&bias[c];
#pragma unroll
        for (int mt = 0; mt < 4; ++mt) {
            int r = m0 + wm * 64 + mt * 16 + grp;
            float2 r0 = make_float2(acc[mt][nt][0] + bv.x, acc[mt][nt][1] + bv.y);
            float2 r1 = make_float2(acc[mt][nt][2] + bv.x, acc[mt][nt][3] + bv.y);
            *(float2*)&C[(size_t)r * N + c]       = r0;
            *(float2*)&C[(size_t)(r + 8) * N + c] = r1;
        }
    }
}

__global__ __launch_bounds__(256, 2)
void gemm_tf32(const float* __restrict__ A, const float* __restrict__ W,
               const float* __restrict__ bias, float* __restrict__ C,
               int M, int K, int N)
{
    gemm_body(A, W, bias, C, M, K, N);
}

__global__ __launch_bounds__(256, 2)
void gemm_qkv(const float* __restrict__ A,
              const float* __restrict__ Wq, const float* __restrict__ Wk,
              const float* __restrict__ Wv,
              const float* __restrict__ bq, const float* __restrict__ bk,
              const float* __restrict__ bv,
              float* __restrict__ q, float* __restrict__ k, float* __restrict__ v)
{
    const float* W; const float* bb; float* C;
    if (blockIdx.z == 0)      { W = Wq; bb = bq; C = q; }
    else if (blockIdx.z == 1) { W = Wk; bb = bk; C = k; }
    else                      { W = Wv; bb = bv; C = v; }
    gemm_body(A, W, bb, C, B_ * S_, E_, E_);
}

// ======================================================================
// Sparse attention v5: 1024 threads = 32 warps per CTA (latency hiding).
//  phase1: S[q][key] split-tf32 mma; 32 warps = 16 key-groups x 2 q-halves
//  phase2: exact top-k, 1 query per warp, redux-based reductions
//  phase3: O = P V split-tf32 mma; 32 warps = 8 key-eighths x 4 d-slices
// ======================================================================
#define SP   1028              // St row stride (== 4 mod 32)
#define QSP  40
#define KP   68                // K-chunk stride (phase-1 A-frags conflict-free)
#define VP   72                // V-chunk stride (phase-3 B-frags conflict-free)

#define ST_F (32 * SP)         // 32896
#define QS_F (64 * QSP)        //  2560
#define KV_F (256 * VP)        // 18432 (max of K/V layouts; red uses 17408)
#define ATTN_SMEM ((ST_F + 2 * QS_F + KV_F) * 4)   // 225792 bytes

__global__ __launch_bounds__(1024, 1)
void attn_kernel()
{
    extern __shared__ float sm[];
    float* St  = sm;                    // [32][SP]   scores then P (fp32)
    float* Qsh = sm + ST_F;             // [64][QSP]  Q^T hi (prescaled)
    float* Qsl = Qsh + QS_F;            // [64][QSP]  Q^T lo
    float* KV  = Qsl + QS_F;            // K chunk [256][KP] / V chunk [256][VP] / red

    const int t    = threadIdx.x;
    const int w    = t >> 5;
    const int lane = t & 31;
    const int grp  = lane >> 2;
    const int tg   = lane & 3;

    const int gid = blockIdx.x;
    const int qt  = gid & 31;
    const int hh  = (gid >> 5) & 7;
    const int b   = gid >> 8;

    const float* Qg = g_q + ((size_t)(b * S_ + qt * QT)) * E_ + hh * D_;
    const float* Kg = g_k + ((size_t)b * S_) * E_ + hh * D_;
    const float* Vg = g_v + ((size_t)b * S_) * E_ + hh * D_;
    float*       Og = g_o + ((size_t)(b * S_ + qt * QT)) * E_ + hh * D_;

    // ---- phase 0: Q^T (prescaled by 1/8) split into hi/lo planes ----
    {
        int qi  = t & 31;
        int dd0 = (t >> 5) * 2;             // 0..62
        float2 v = *(const float2*)(Qg + (size_t)qi * E_ + dd0);
        float h, l;
        split2(v.x * 0.125f, h, l); Qsh[dd0*QSP+qi] = h;     Qsl[dd0*QSP+qi] = l;
        split2(v.y * 0.125f, h, l); Qsh[(dd0+1)*QSP+qi] = h; Qsl[(dd0+1)*QSP+qi] = l;
    }
    __syncthreads();

    // ---- phase 1: scores; warp = (wk key-group of 16, wq query-half of 16)
    {
        const int wk = w >> 1;              // 0..15
        const int wq = w & 1;               // 0..1
        const int rbase = wk * 16 + grp;

        for (int kc = 0; kc < S_; kc += 256) {
#pragma unroll
            for (int i = 0; i < 4; ++i) {
                int idx = t + i * 1024;
                int kj  = idx >> 4;
                int dd0 = (idx & 15) * 4;
                *(float4*)&KV[kj * KP + dd0] =
                    *(const float4*)(Kg + (size_t)(kc + kj) * E_ + dd0);
            }
            __syncthreads();

            float acc[2][4];
#pragma unroll
            for (int nt = 0; nt < 2; ++nt)
#pragma unroll
                for (int c = 0; c < 4; ++c) acc[nt][c] = 0.f;

#pragma unroll
            for (int ks = 0; ks < 8; ++ks) {
                const int ka = ks * 8 + tg;
                float x0 = KV[rbase * KP + ka];
                float x1 = KV[(rbase + 8) * KP + ka];
                float x2 = KV[rbase * KP + ka + 4];
                float x3 = KV[(rbase + 8) * KP + ka + 4];
                float h0, l0, h1, l1, h2, l2, h3, l3;
                split2(x0, h0, l0); split2(x1, h1, l1);
                split2(x2, h2, l2); split2(x3, h3, l3);
                unsigned ah0 = fu(h0), ah1 = fu(h1), ah2 = fu(h2), ah3 = fu(h3);
                unsigned al0 = fu(l0), al1 = fu(l1), al2 = fu(l2), al3 = fu(l3);
#pragma unroll
                for (int nt = 0; nt < 2; ++nt) {
                    const int qcol = wq * 16 + nt * 8 + grp;
                    unsigned bh0 = fu(Qsh[ka * QSP + qcol]);
                    unsigned bh1 = fu(Qsh[(ka + 4) * QSP + qcol]);
                    unsigned bl0 = fu(Qsl[ka * QSP + qcol]);
                    unsigned bl1 = fu(Qsl[(ka + 4) * QSP + qcol]);
                    mma_tf32(acc[nt], ah0, ah1, ah2, ah3, bh0, bh1);
                    mma_tf32(acc[nt], ah0, ah1, ah2, ah3, bl0, bl1);
                    mma_tf32(acc[nt], al0, al1, al2, al3, bh0, bh1);
                }
            }
            const int key = kc + wk * 16 + grp;
#pragma unroll
            for (int nt = 0; nt < 2; ++nt) {
                const int q = wq * 16 + nt * 8 + 2 * tg;
                St[q * SP + key]           = acc[nt][0];
                St[(q + 1) * SP + key]     = acc[nt][1];
                St[q * SP + key + 8]       = acc[nt][2];
                St[(q + 1) * SP + key + 8] = acc[nt][3];
            }
            __syncthreads();
        }
    }

    // ---- phase 2: exact top-k + softmax; warp w owns query w ----
    {
        const int qi = w;
        float* row = St + (size_t)qi * SP;

        unsigned u[32];
        unsigned umax = 0u, umin = 0xFFFFFFFFu;
#pragma unroll
        for (int i = 0; i < 32; ++i) {
            u[i] = fmap(row[lane + 32 * i]);
            umax = max(umax, u[i]);
            umin = min(umin, u[i]);
        }
        umax = __reduce_max_sync(0xFFFFFFFFu, umax);
        umin = __reduce_min_sync(0xFFFFFFFFu, umin);

        unsigned lo = umin, hi = umax;
        while (lo < hi) {
            unsigned mid = lo + ((hi - lo + 1) >> 1);
            unsigned c = 0;
#pragma unroll
            for (int i = 0; i < 32; ++i) c += (u[i] >= mid);
            c = __reduce_add_sync(0xFFFFFFFFu, c);
            if (c >= KTOP) lo = mid; else hi = mid - 1;
        }
        const unsigned thr = lo;
        const float mf = unfmap(umax);

        float sum = 0.f;
#pragma unroll
        for (int i = 0; i < 32; ++i) {
            float ev = 0.f;
            if (u[i] >= thr) ev = __expf(unfmap(u[i]) - mf);
            u[i] = __float_as_uint(ev);
            sum += ev;
        }
#pragma unroll
        for (int off = 16; off > 0; off >>= 1)
            sum += __shfl_xor_sync(0xFFFFFFFFu, sum, off);
        const float inv = 1.f / sum;

#pragma unroll
        for (int i = 0; i < 32; ++i)
            row[lane + 32 * i] = __uint_as_float(u[i]) * inv;
    }
    __syncthreads();

    // ---- phase 3: O = P V ; warp = (kg key-eighth, wn d-slice of 16) ----
    {
        const int kg = w >> 2;              // 0..7
        const int wn = w & 3;               // 0..3

        float acc[2][2][4];
#pragma unroll
        for (int mt = 0; mt < 2; ++mt)
#pragma unroll
            for (int nt = 0; nt < 2; ++nt)
#pragma unroll
                for (int c = 0; c < 4; ++c) acc[mt][nt][c] = 0.f;

        for (int kc = 0; kc < S_; kc += 256) {
#pragma unroll
            for (int i = 0; i < 4; ++i) {
                int idx = t + i * 1024;
                int kj  = idx >> 4;
                int dd0 = (idx & 15) * 4;
                *(float4*)&KV[kj * VP + dd0] =
                    *(const float4*)(Vg + (size_t)(kc + kj) * E_ + dd0);
            }
            __syncthreads();

#pragma unroll
            for (int ks = 0; ks < 4; ++ks) {
                const int kl = kg * 32 + ks * 8;
                const int k0 = kc + kl;

                unsigned bh[2][2], bl[2][2];
#pragma unroll
                for (int nt = 0; nt < 2; ++nt) {
                    const int col = wn * 16 + nt * 8 + grp;
                    float y0 = KV[(kl + tg) * VP + col];
                    float y1 = KV[(kl + tg + 4) * VP + col];
                    float h0, l0, h1, l1;
                    split2(y0, h0, l0); split2(y1, h1, l1);
                    bh[nt][0] = fu(h0); bh[nt][1] = fu(h1);
                    bl[nt][0] = fu(l0); bl[nt][1] = fu(l1);
                }
#pragma unroll
                for (int mt = 0; mt < 2; ++mt) {
                    float p0 = St[(mt * 16 + grp) * SP + k0 + tg];
                    float p1 = St[(mt * 16 + grp + 8) * SP + k0 + tg];
                    float p2 = St[(mt * 16 + grp) * SP + k0 + tg + 4];
                    float p3 = St[(mt * 16 + grp + 8) * SP + k0 + tg + 4];
                    float h0, l0, h1, l1, h2, l2, h3, l3;
                    split2(p0, h0, l0); split2(p1, h1, l1);
                    split2(p2, h2, l2); split2(p3, h3, l3);
                    unsigned ah0 = fu(h0), ah1 = fu(h1), ah2 = fu(h2), ah3 = fu(h3);
                    unsigned al0 = fu(l0), al1 = fu(l1), al2 = fu(l2), al3 = fu(l3);
#pragma unroll
                    for (int nt = 0; nt < 2; ++nt) {
                        mma_tf32(acc[mt][nt], ah0, ah1, ah2, ah3, bh[nt][0], bh[nt][1]);
                        mma_tf32(acc[mt][nt], ah0, ah1, ah2, ah3, bl[nt][0], bl[nt][1]);
                        mma_tf32(acc[mt][nt], al0, al1, al2, al3, bh[nt][0], bh[nt][1]);
                    }
                }
            }
            __syncthreads();
        }

        // reduce 8 key-eighths via smem (reuse KV region; stride 68)
        float* red = KV;                    // [8][32][68] = 17408 floats
#pragma unroll
        for (int mt = 0; mt < 2; ++mt)
#pragma unroll
            for (int nt = 0; nt < 2; ++nt) {
                const int q = mt * 16 + grp;
                const int d = wn * 16 + nt * 8 + 2 * tg;
                *(float2*)&red[kg * 2176 + q * 68 + d] =
                    make_float2(acc[mt][nt][0], acc[mt][nt][1]);
                *(float2*)&red[kg * 2176 + (q + 8) * 68 + d] =
                    make_float2(acc[mt][nt][2], acc[mt][nt][3]);
            }
        __syncthreads();

#pragma unroll
        for (int kk = 0; kk < 2; ++kk) {
            int m  = t + kk * 1024;
            int qi = m >> 6, dd = m & 63;
            float s = 0.f;
#pragma unroll
            for (int g = 0; g < 8; ++g)
                s += red[g * 2176 + qi * 68 + dd];
            Og[(size_t)qi * E_ + dd] = s;
        }
    }
}

// ======================================================================
// mean pool + final FC
// ======================================================================
__global__ void meanpool_k(const float* __restrict__ h, float* __restrict__ pool)
{
    __shared__ float red[512];
    const int b = blockIdx.y;
    const int e = blockIdx.x * 128 + (threadIdx.x & 127);
    const int slice = threadIdx.x >> 7;
    const float* base = h + (size_t)b * S_ * E_ + e;
    float s = 0.f;
#pragma unroll 8
    for (int i = 0; i < 256; ++i)
        s += base[(size_t)(slice * 256 + i) * E_];
    red[threadIdx.x] = s;
    __syncthreads();
    if (slice == 0) {
        float tot = red[threadIdx.x] + red[threadIdx.x + 128] +
                    red[threadIdx.x + 256] + red[threadIdx.x + 384];
        pool[b * E_ + e] = tot * (1.f / (float)S_);
    }
}

__global__ void fc_k(const float* __restrict__ pool, const float* __restrict__ w,
                     const float* __restrict__ bias, float* __restrict__ out)
{
    int t = threadIdx.x;
    if (t >= B_ * NCLS) return;
    int b = t / NCLS, c = t % NCLS;
    float s = bias[c];
    const float* p = pool + b * E_;
#pragma unroll 8
    for (int k = 0; k < E_; ++k)
        s += p[k] * w[k * NCLS + c];
    out[t] = s;
}

// ======================================================================
// launch
// ======================================================================
extern "C" void kernel_launch(void* const* d_in, const int* in_sizes, int n_in,
                              void* d_out, int out_size)
{
    (void)in_sizes; (void)n_in; (void)out_size;

    const float* x     = (const float*)d_in[0];
    const float* emb_w = (const float*)d_in[1];
    const float* emb_b = (const float*)d_in[2];
    const float* Wq    = (const float*)d_in[3];
    const float* Wk    = (const float*)d_in[4];
    const float* Wv    = (const float*)d_in[5];
    const float* Wo    = (const float*)d_in[6];
    const float* bq    = (const float*)d_in[7];
    const float* bk    = (const float*)d_in[8];
    const float* bv    = (const float*)d_in[9];
    const float* bo    = (const float*)d_in[10];
    const float* fc_w  = (const float*)d_in[11];
    const float* fc_b  = (const float*)d_in[12];
    float* out = (float*)d_out;

    float *h, *q, *k, *v, *o, *pool;
    cudaGetSymbolAddress((void**)&h,    g_h);
    cudaGetSymbolAddress((void**)&q,    g_q);
    cudaGetSymbolAddress((void**)&k,    g_k);
    cudaGetSymbolAddress((void**)&v,    g_v);
    cudaGetSymbolAddress((void**)&o,    g_o);
    cudaGetSymbolAddress((void**)&pool, g_pool);

    cudaFuncSetAttribute(attn_kernel, cudaFuncAttributeMaxDynamicSharedMemorySize, ATTN_SMEM);
    cudaFuncSetAttribute(gemm_tf32,   cudaFuncAttributeMaxDynamicSharedMemorySize, GEMM_SMEM);
    cudaFuncSetAttribute(gemm_qkv,    cudaFuncAttributeMaxDynamicSharedMemorySize, GEMM_SMEM);

    const int M = B_ * S_;                          // 8192
    dim3 ggrid(E_ / 128, M / 128);                  // (4, 64)
    dim3 qkvgrid(E_ / 128, M / 128, 3);

    gemm_tf32<<<ggrid, 256, GEMM_SMEM>>>(x, emb_w, emb_b, h, M, FIN, E_);

    for (int l = 0; l < L_; ++l) {
        const size_t wo  = (size_t)l * E_ * E_;
        const size_t bo_ = (size_t)l * E_;
        gemm_qkv<<<qkvgrid, 256, GEMM_SMEM>>>(h, Wq + wo, Wk + wo, Wv + wo,
                                              bq + bo_, bk + bo_, bv + bo_, q, k, v);
        attn_kernel<<<B_ * H_ * (S_ / QT), 1024, ATTN_SMEM>>>();
        gemm_tf32<<<ggrid, 256, GEMM_SMEM>>>(o, Wo + wo, bo + bo_, h, M, E_, E_);
    }

    meanpool_k<<<dim3(E_ / 128, B_), 512>>>(h, pool);
    fc_k<<<1, 128>>>(pool, fc_w, fc_b, out);
}